// round 14
// baseline (speedup 1.0000x reference)
#include <cuda_runtime.h>
#include <math.h>

#define NF   24
#define FS   8
#define DY   32
#define DX   32
#define SEQL 300
#define TOTAL (NF*FS*DY*DX*SEQL)   // 58,982,400 floats
#define N4    (TOTAL/4)            // 14,745,600 float4
#define ROW4  75

#define B1    888                  // 148 SMs * 6 blocks — co-resident at <=42 regs
#define THR   256
#define NW    (B1*8)               // 7104 warps

#define RND       128              // float4 per warp-round (4 per lane, imm offsets)
#define NCH       (N4/RND)         // 115200 rounds total
#define SROUNDS   14               // static rounds per warp
#define STATIC_CH (NW*SROUNDS)     // 99456
#define NSTEAL    ((NCH-STATIC_CH)/4)  // 3936 steal groups of 4 rounds

#define FS_STRIDE (DY*DX*SEQL)     // 307200 floats between fs slices
#define B_POS     (NF*16*10)       // 3840 bbox spatial positions

__device__ float    g_partial[B1];
__device__ unsigned g_count;           // returns to 0 every run (zero-init)
__device__ unsigned g_chunk;           // steal counter; reset by barrier releaser
__device__ volatile unsigned g_sense;  // sense-reversing barrier

// Hand-evaluated Python bbox math: left = int(32*l), w = int(32*round(l+0.3,4)) - left
__constant__ int c_left[NF] = {
    1, 2, 2, 3, 4, 5, 5, 6, 7, 7, 8, 9,
    9, 10, 11, 12, 12, 13, 14, 14, 15, 16, 16, 17
};
__constant__ int c_w[NF] = {
    10, 9, 10, 10, 9, 9, 10, 10, 9, 10, 10, 9,
    10, 10, 9, 9, 10, 10, 9, 10, 10, 9, 10, 10
};
__constant__ int c_edge_tok[6] = {2, 3, 9, 10, 11, 108};

__device__ __forceinline__ bool sel_tok(int s) {
    return ((unsigned)(s - 9) < 100u) || ((s & ~1) == 2);
}

// weaken multipliers for float4 slot j = i % 75 (seq 4j..4j+3)
__device__ __forceinline__ float4 mult_for(int j) {
    int s0 = j * 4;
    float4 m;
    m.x = sel_tok(s0    ) ? 0.918f : 1.0f;
    m.y = sel_tok(s0 + 1) ? 0.918f : 1.0f;
    m.z = sel_tok(s0 + 2) ? 0.918f : 1.0f;
    m.w = sel_tok(s0 + 3) ? 0.918f : 1.0f;
    return m;
}

// normalized gaussian weight for (yrow, xoff) given bbox width w (9 or 10)
__device__ __forceinline__ float gauss_w(int yrow, int xoff, int w) {
    const float dx = (float)yrow * (16.0f / 15.0f) - 8.0f;
    float ax = ((8.0f / 15.0f) * (8.0f / 15.0f) - dx * dx) * (9.0f / 512.0f);
    float dy, dymin2, inv2sy2;
    if (w == 10) {
        dy = (float)xoff * (10.0f / 9.0f) - 5.0f;
        dymin2 = (5.0f / 9.0f) * (5.0f / 9.0f);
        inv2sy2 = 9.0f / 200.0f;
    } else {
        dy = (float)xoff * (9.0f / 8.0f) - 4.0f;
        dymin2 = 0.25f;
        inv2sy2 = 1.0f / 18.0f;
    }
    return __expf(ax + (dymin2 - dy * dy) * inv2sy2);
}

// one warp-round: 128 consecutive float4; lane + {0,32,64,96} -> base reg +
// 512/1024/1536B immediate offsets; 4 LDG.128 batched (MLP 4).
__device__ __forceinline__ void stream_round(
    const float4* __restrict__ in4, float4* __restrict__ out4,
    int base, int lane, float& mx)
{
    const int i0 = base + lane;
    float4 v[4];
    #pragma unroll
    for (int u = 0; u < 4; u++) v[u] = __ldcs(in4 + i0 + u * 32);
    #pragma unroll
    for (int u = 0; u < 4; u++) {
        float4 x = v[u];
        mx = fmaxf(mx, fmaxf(fmaxf(x.x, x.y), fmaxf(x.z, x.w)));
        float4 m = mult_for((i0 + u * 32) % ROW4);
        __stcs(out4 + i0 + u * 32,
               make_float4(x.x * m.x, x.y * m.y, x.z * m.z, x.w * m.w));
    }
}

__global__ void __launch_bounds__(THR, 6)
fused_kernel(const float4* __restrict__ in4, float4* __restrict__ out4,
             const float* __restrict__ in, float* __restrict__ out) {
    const int tid  = threadIdx.x;
    const int bid  = blockIdx.x;
    const int lane = tid & 31;
    const int wid  = tid >> 5;
    const int gw   = bid * 8 + wid;       // global warp id [0, 7104)
    const unsigned cur_sense = g_sense;   // read before anyone flips it

    __shared__ float sm[8];
    __shared__ float s_gmax;

    // ===== phase 1a: static warp-chunk stream (86% of work, MLP 4) ==========
    float mx = 0.f;
    #pragma unroll 2
    for (int r = 0; r < SROUNDS; r++)
        stream_round(in4, out4, (gw + r * NW) * RND, lane, mx);

    // ===== phase 1b: stolen tail (14%, balances barrier arrival) ============
    unsigned c;
    if (lane == 0) c = atomicAdd(&g_chunk, 1u);
    c = __shfl_sync(0xffffffffu, c, 0);
    while (c < NSTEAL) {
        const int base = (STATIC_CH + (int)c * 4) * RND;
        stream_round(in4, out4, base,           lane, mx);
        stream_round(in4, out4, base + RND,     lane, mx);
        stream_round(in4, out4, base + RND * 2, lane, mx);
        stream_round(in4, out4, base + RND * 3, lane, mx);
        if (lane == 0) c = atomicAdd(&g_chunk, 1u);
        c = __shfl_sync(0xffffffffu, c, 0);
    }

    // block max -> g_partial[bid]
    #pragma unroll
    for (int off = 16; off; off >>= 1)
        mx = fmaxf(mx, __shfl_xor_sync(0xffffffffu, mx, off));
    if (lane == 0) sm[wid] = mx;
    __syncthreads();
    if (tid < 8) {
        mx = sm[tid];
        #pragma unroll
        for (int off = 4; off; off >>= 1)
            mx = fmaxf(mx, __shfl_xor_sync(0xffu, mx, off));
        if (tid == 0) g_partial[bid] = mx;
    }

    // ================= grid-wide barrier (sense-reversing) ===================
    __syncthreads();
    if (tid == 0) {
        __threadfence();                                  // publish g_partial
        unsigned old = atomicAdd(&g_count, 1);
        if (old == B1 - 1) {
            g_count = 0;                                  // reset for next replay
            g_chunk = 0;                                  // reset steal counter
            __threadfence();
            g_sense = cur_sense ^ 1u;                     // release
        } else {
            while (g_sense == cur_sense) __nanosleep(64);
            __threadfence();                              // acquire
        }
    }
    __syncthreads();

    // ================= global max from 888 partials ==========================
    float pm = 0.f;
    for (int j = tid; j < B1; j += THR)                   // 4 strided reads
        pm = fmaxf(pm, __ldcg(&g_partial[j]));
    #pragma unroll
    for (int off = 16; off; off >>= 1)
        pm = fmaxf(pm, __shfl_xor_sync(0xffffffffu, pm, off));
    if (lane == 0) sm[wid] = pm;
    __syncthreads();
    if (tid < 8) {
        pm = sm[tid];
        #pragma unroll
        for (int off = 4; off; off >>= 1)
            pm = fmaxf(pm, __shfl_xor_sync(0xffu, pm, off));
        if (tid == 0) s_gmax = pm;
    }
    __syncthreads();
    const float gmax = s_gmax;

    // ===== phase 2: strengthen. warp per position (3840), 2 groups of 4 rows =
    if (gw >= B_POS) return;
    int pos = gw;
    const int xoff = pos % 10;  pos /= 10;
    const int yrow = pos & 15;
    const int f    = pos >> 4;
    const int w    = c_w[f];
    if (xoff >= w) return;                // warp-uniform

    const float add = 0.125f * gauss_w(yrow, xoff, w) * gmax;

    #pragma unroll
    for (int h = 0; h < 2; h++) {
        const long base = (long)((f * FS + h * 4) * DY + 8 + yrow) * DX * SEQL
                        + (long)(c_left[f] + xoff) * SEQL;
        if (lane < 24) {
            const int tok = 12 + 4 * lane;    // 16B-aligned: row*300 ≡ 0 mod 4
            float4 v[4];
            #pragma unroll
            for (int r = 0; r < 4; r++)
                v[r] = __ldcs((const float4*)(in + base + (long)r * FS_STRIDE + tok));
            #pragma unroll
            for (int r = 0; r < 4; r++)
                __stcs((float4*)(out + base + (long)r * FS_STRIDE + tok),
                       make_float4(v[r].x + add, v[r].y + add,
                                   v[r].z + add, v[r].w + add));
        } else if (lane < 30) {
            const int tok = c_edge_tok[lane - 24];
            float v[4];
            #pragma unroll
            for (int r = 0; r < 4; r++)
                v[r] = __ldcs(in + base + (long)r * FS_STRIDE + tok);
            #pragma unroll
            for (int r = 0; r < 4; r++)
                __stcs(out + base + (long)r * FS_STRIDE + tok, v[r] + add);
        }
    }
}

extern "C" void kernel_launch(void* const* d_in, const int* in_sizes, int n_in,
                              void* d_out, int out_size) {
    const float* in = (const float*)d_in[0];
    float* out = (float*)d_out;
    fused_kernel<<<B1, THR>>>((const float4*)in, (float4*)out, in, out);
}

// round 15
// speedup vs baseline: 1.0635x; 1.0635x over previous
#include <cuda_runtime.h>
#include <math.h>

#define NF   24
#define FS   8
#define DY   32
#define DX   32
#define SEQL 300
#define TOTAL (NF*FS*DY*DX*SEQL)   // 58,982,400 floats
#define N4    (TOTAL/4)            // 14,745,600 float4
#define ROW4  75

#define A_THREADS 256
#define A_ILP     4
#define A_BLOCKS  (N4 / (A_THREADS * A_ILP))   // 14400
// stride = 3,686,400 = 75 * 49152 -> idx%75 invariant over ILP slots

// Pass B: one warp per bbox position (all 8 fs rows), 3840 warps.
#define B_THREADS 256
#define B_BLOCKS  (NF * 16 * 10 / 8)           // 480
#define FS_STRIDE (DY*DX*SEQL)                 // 307200 floats between fs slices

__device__ float g_max;   // reset to 0 via memset each replay (inputs >= 0)

// Hand-evaluated Python bbox math: left = int(32*l), w = int(32*round(l+0.3,4)) - left
__constant__ int c_left[NF] = {
    1, 2, 2, 3, 4, 5, 5, 6, 7, 7, 8, 9,
    9, 10, 11, 12, 12, 13, 14, 14, 15, 16, 16, 17
};
__constant__ int c_w[NF] = {
    10, 9, 10, 10, 9, 9, 10, 10, 9, 10, 10, 9,
    10, 10, 9, 9, 10, 10, 9, 10, 10, 9, 10, 10
};
__constant__ int c_edge_tok[6] = {2, 3, 9, 10, 11, 108};

__device__ __forceinline__ bool sel_tok(int s) {
    return ((unsigned)(s - 9) < 100u) || ((s & ~1) == 2);
}

// Pass A (R7 form, ~7.1 TB/s): out = in * (sel ? 0.918 : 1.0) + grid max.
__global__ void __launch_bounds__(A_THREADS)
apply_weaken_max(const float4* __restrict__ in, float4* __restrict__ out) {
    const int t      = blockIdx.x * A_THREADS + threadIdx.x;
    const int stride = A_BLOCKS * A_THREADS;

    const int s0 = (t % ROW4) * 4;     // invariant across ILP slots
    float4 m;
    m.x = sel_tok(s0    ) ? 0.918f : 1.0f;
    m.y = sel_tok(s0 + 1) ? 0.918f : 1.0f;
    m.z = sel_tok(s0 + 2) ? 0.918f : 1.0f;
    m.w = sel_tok(s0 + 3) ? 0.918f : 1.0f;

    float4 v[A_ILP];
    #pragma unroll
    for (int k = 0; k < A_ILP; k++) v[k] = __ldcs(in + t + k * stride);

    float mx = 0.f;
    #pragma unroll
    for (int k = 0; k < A_ILP; k++) {
        float4 x = v[k];
        mx = fmaxf(mx, fmaxf(fmaxf(x.x, x.y), fmaxf(x.z, x.w)));
        __stcs(out + t + k * stride,
               make_float4(x.x * m.x, x.y * m.y, x.z * m.z, x.w * m.w));
    }

    #pragma unroll
    for (int off = 16; off; off >>= 1)
        mx = fmaxf(mx, __shfl_xor_sync(0xffffffffu, mx, off));
    __shared__ float sm[A_THREADS / 32];
    if ((threadIdx.x & 31) == 0) sm[threadIdx.x >> 5] = mx;
    __syncthreads();
    if (threadIdx.x < (A_THREADS / 32)) {
        mx = sm[threadIdx.x];
        #pragma unroll
        for (int off = (A_THREADS / 64); off; off >>= 1)
            mx = fmaxf(mx, __shfl_xor_sync(0xffffffffu, mx, off));
        if (threadIdx.x == 0)
            atomicMax((int*)&g_max, __float_as_int(mx));   // inputs >= 0
    }

    // allow the dependent strengthen kernel to start launching as we drain
    cudaTriggerProgrammaticLaunchCompletion();
}

// Pass B (PDL secondary): one warp per bbox position, all 8 fs-rows.
// Prefetch `in` + compute gaussian BEFORE the grid dependency sync (input is
// read-only; inside the bbox out==in since weaken=1 there), then sync, read
// g_max, and store. Exposed cost ≈ stores only.
__global__ void __launch_bounds__(B_THREADS)
apply_strengthen(const float* __restrict__ in, float* __restrict__ out) {
    const int W    = (blockIdx.x * B_THREADS + threadIdx.x) >> 5;  // [0,3840)
    const int lane = threadIdx.x & 31;

    int pos = W;
    const int xoff = pos % 10;  pos /= 10;
    const int yrow = pos & 15;
    const int f    = pos >> 4;
    const int w    = c_w[f];
    const bool active = (xoff < w);        // warp-uniform

    long  base = 0;
    float gauss = 0.f;
    float4 v4[FS];
    float  vs[FS];
    const int tok4 = 12 + 4 * lane;                                  // lane<24
    const int toke = (lane >= 24 && lane < 30) ? c_edge_tok[lane - 24] : 0;

    if (active) {
        base = (long)(f * FS * DY + 8 + yrow) * DX * SEQL
             + (long)(c_left[f] + xoff) * SEQL;

        // prefetch (independent of pass A)
        if (lane < 24) {
            #pragma unroll
            for (int r = 0; r < FS; r++)
                v4[r] = __ldcs((const float4*)(in + base + (long)r * FS_STRIDE + tok4));
        } else if (lane < 30) {
            #pragma unroll
            for (int r = 0; r < FS; r++)
                vs[r] = __ldcs(in + base + (long)r * FS_STRIDE + toke);
        }

        // normalized gaussian, fp32, one MUFU
        const float dx = (float)yrow * (16.0f / 15.0f) - 8.0f;
        float ax = ((8.0f / 15.0f) * (8.0f / 15.0f) - dx * dx) * (9.0f / 512.0f);
        float dy, dymin2, inv2sy2;
        if (w == 10) {
            dy = (float)xoff * (10.0f / 9.0f) - 5.0f;
            dymin2 = (5.0f / 9.0f) * (5.0f / 9.0f);
            inv2sy2 = 9.0f / 200.0f;
        } else {
            dy = (float)xoff * (9.0f / 8.0f) - 4.0f;
            dymin2 = 0.25f;
            inv2sy2 = 1.0f / 18.0f;
        }
        gauss = __expf(ax + (dymin2 - dy * dy) * inv2sy2);
    }

    // wait until pass A (and its g_max / out stores) is fully visible
    cudaGridDependencySynchronize();

    if (!active) return;
    const float add = 0.125f * gauss * g_max;

    if (lane < 24) {
        #pragma unroll
        for (int r = 0; r < FS; r++)
            __stcs((float4*)(out + base + (long)r * FS_STRIDE + tok4),
                   make_float4(v4[r].x + add, v4[r].y + add,
                               v4[r].z + add, v4[r].w + add));
    } else if (lane < 30) {
        #pragma unroll
        for (int r = 0; r < FS; r++)
            __stcs(out + base + (long)r * FS_STRIDE + toke, vs[r] + add);
    }
}

extern "C" void kernel_launch(void* const* d_in, const int* in_sizes, int n_in,
                              void* d_out, int out_size) {
    const float* in = (const float*)d_in[0];
    float* out = (float*)d_out;

    static void* gmax_addr = nullptr;
    if (!gmax_addr) cudaGetSymbolAddress(&gmax_addr, g_max);

    cudaMemsetAsync(gmax_addr, 0, sizeof(float));
    apply_weaken_max<<<A_BLOCKS, A_THREADS>>>((const float4*)in, (float4*)out);

    // PDL secondary: allowed to launch while pass A drains
    cudaLaunchConfig_t cfg = {};
    cfg.gridDim  = dim3(B_BLOCKS);
    cfg.blockDim = dim3(B_THREADS);
    cudaLaunchAttribute attr[1];
    attr[0].id = cudaLaunchAttributeProgrammaticStreamSerialization;
    attr[0].val.programmaticStreamSerializationAllowed = 1;
    cfg.attrs = attr;
    cfg.numAttrs = 1;
    cudaLaunchKernelEx(&cfg, apply_strengthen, in, out);
}